// round 13
// baseline (speedup 1.0000x reference)
#include <cuda_runtime.h>
#include <cstdint>

// Problem constants
#define B_    128
#define T_    512
#define DIN   512
#define DOUT  512
#define BETA  0.95f
#define THRESH 1.0f

#define N_SPK ((size_t)B_ * T_ * DOUT)   // 33554432

__device__ int g_count;

// ---------------------------------------------------------------------------
// Fused GEMM+scan. CTA = (n-block of 64, batch b), 128 threads, 4 t-tiles of
// 128 serial. Mainloop = R9's proven FFMA2 ascending-k body (8x8 microtile,
// 2 B/FFMA2 LDS -> not crossbar-bound, unlike R11's 4x8).
// ---------------------------------------------------------------------------
#define BK   16
#define NKC  (DIN / BK)       // 32 k-chunks
#define LDA  132              // As row stride (floats)
#define LDB  68               // Bs row stride (floats)
#define LDS_STG 66            // staging row stride (floats)

#define AS_FL  (2 * BK * LDA)          // 4224 floats
#define BS_FL  (2 * BK * LDB)          // 2176 floats
#define STG_FL (64 * LDS_STG)          // 4224 floats
#define SMEM_BYTES ((AS_FL + BS_FL + STG_FL) * 4)   // 42496

typedef unsigned long long ull;

static __device__ __forceinline__ ull splat2(float v) {
    ull r;
    asm("mov.b64 %0, {%1, %1};" : "=l"(r) : "f"(v));
    return r;
}
static __device__ __forceinline__ ull fma2(ull a, ull b, ull c) {
    ull d;
    asm("fma.rn.f32x2 %0, %1, %2, %3;" : "=l"(d) : "l"(a), "l"(b), "l"(c));
    return d;
}
static __device__ __forceinline__ float2 unpack2(ull v) {
    float lo, hi;
    asm("mov.b64 {%0, %1}, %2;" : "=f"(lo), "=f"(hi) : "l"(v));
    return make_float2(lo, hi);
}

__global__ __launch_bounds__(128, 4)
void fused_kernel(const float* __restrict__ x,
                  const float* __restrict__ W,
                  const float* __restrict__ bias,
                  float* __restrict__ out)
{
    extern __shared__ float sm[];
    float* As  = sm;                   // [2][BK*LDA]  As[buf][k*132 + t]
    float* Bs  = sm + AS_FL;           // [2][BK*LDB]  Bs[buf][k*68 + n]
    float* stg = sm + AS_FL + BS_FL;   // [64][LDS_STG]

    const int tid = threadIdx.x;
    const int tx  = tid & 7;           // n microtile (8 cols)
    const int ty  = tid >> 3;          // t microtile (8 rows), 0..15
    const int n0  = blockIdx.x * 64;
    const int b   = blockIdx.y;

    // bias for this thread's 8 columns
    const int nb = n0 + tx * 8;
    float rbias[8];
    #pragma unroll
    for (int j = 0; j < 8; j++) rbias[j] = bias[nb + j];

    // LIF state (threads 0..63 own column d = n0 + tid)
    float mem = 0.0f;
    int   cnt = 0;

    // global-load coords
    const int a_row = tid >> 2;        // + it*32? no: idx scheme below
    const int a_kq  = tid & 3;
    (void)a_row; (void)a_kq;

    for (int tile = 0; tile < 4; tile++) {
        const int t0 = tile * 128;
        const float* Abase = x + (size_t)(b * T_ + t0) * DIN;
        const float* Wbase = W + (size_t)n0 * DIN;

        ull acc2[8][4];
        #pragma unroll
        for (int i = 0; i < 8; i++)
            #pragma unroll
            for (int j = 0; j < 4; j++) acc2[i][j] = 0ull;

        float4 pa[4], pb[2];

        // ---- prologue: chunk 0 -> buf 0 ----
        #pragma unroll
        for (int it = 0; it < 4; it++) {
            int idx = tid + it * 128;          // 0..511
            int r   = idx >> 2;                // t-row 0..127
            int kq  = idx & 3;
            pa[it] = *(const float4*)(&Abase[(size_t)r * DIN + kq * 4]);
        }
        #pragma unroll
        for (int it = 0; it < 2; it++) {
            int idx = tid + it * 128;          // 0..255
            int r   = idx >> 2;                // n-row 0..63
            int kq  = idx & 3;
            pb[it] = *(const float4*)(&Wbase[(size_t)r * DIN + kq * 4]);
        }
        #pragma unroll
        for (int it = 0; it < 4; it++) {
            int idx = tid + it * 128;
            int r   = idx >> 2;
            int kq  = idx & 3;
            As[(kq * 4 + 0) * LDA + r] = pa[it].x;
            As[(kq * 4 + 1) * LDA + r] = pa[it].y;
            As[(kq * 4 + 2) * LDA + r] = pa[it].z;
            As[(kq * 4 + 3) * LDA + r] = pa[it].w;
        }
        #pragma unroll
        for (int it = 0; it < 2; it++) {
            int idx = tid + it * 128;
            int r   = idx >> 2;
            int kq  = idx & 3;
            Bs[(kq * 4 + 0) * LDB + r] = pb[it].x;
            Bs[(kq * 4 + 1) * LDB + r] = pb[it].y;
            Bs[(kq * 4 + 2) * LDB + r] = pb[it].z;
            Bs[(kq * 4 + 3) * LDB + r] = pb[it].w;
        }
        __syncthreads();

        // ---- k-chunk mainloop ----
        for (int kc = 0; kc < NKC; kc++) {
            const int buf = kc & 1;
            const bool pf = (kc + 1 < NKC);
            if (pf) {
                const int k0 = (kc + 1) * BK;
                #pragma unroll
                for (int it = 0; it < 4; it++) {
                    int idx = tid + it * 128;
                    int r   = idx >> 2;
                    int kq  = idx & 3;
                    pa[it] = *(const float4*)(&Abase[(size_t)r * DIN + k0 + kq * 4]);
                }
                #pragma unroll
                for (int it = 0; it < 2; it++) {
                    int idx = tid + it * 128;
                    int r   = idx >> 2;
                    int kq  = idx & 3;
                    pb[it] = *(const float4*)(&Wbase[(size_t)r * DIN + k0 + kq * 4]);
                }
            }

            const float* Ab = As + buf * (BK * LDA);
            const float* Bb = Bs + buf * (BK * LDB);
            #pragma unroll
            for (int k = 0; k < BK; k++) {
                const float* ar = &Ab[k * LDA + ty * 8];
                const float* br = &Bb[k * LDB + tx * 8];
                float4 ra0 = *(const float4*)(ar);
                float4 ra1 = *(const float4*)(ar + 4);
                ulonglong2 rb0 = *(const ulonglong2*)(br);
                ulonglong2 rb1 = *(const ulonglong2*)(br + 4);
                const float ras[8] = {ra0.x, ra0.y, ra0.z, ra0.w,
                                      ra1.x, ra1.y, ra1.z, ra1.w};
                #pragma unroll
                for (int i = 0; i < 8; i++) {
                    const ull pav = splat2(ras[i]);
                    acc2[i][0] = fma2(pav, rb0.x, acc2[i][0]);
                    acc2[i][1] = fma2(pav, rb0.y, acc2[i][1]);
                    acc2[i][2] = fma2(pav, rb1.x, acc2[i][2]);
                    acc2[i][3] = fma2(pav, rb1.y, acc2[i][3]);
                }
            }

            if (pf) {
                const int nbuf = buf ^ 1;
                float* Aw = As + nbuf * (BK * LDA);
                float* Bw = Bs + nbuf * (BK * LDB);
                #pragma unroll
                for (int it = 0; it < 4; it++) {
                    int idx = tid + it * 128;
                    int r   = idx >> 2;
                    int kq  = idx & 3;
                    Aw[(kq * 4 + 0) * LDA + r] = pa[it].x;
                    Aw[(kq * 4 + 1) * LDA + r] = pa[it].y;
                    Aw[(kq * 4 + 2) * LDA + r] = pa[it].z;
                    Aw[(kq * 4 + 3) * LDA + r] = pa[it].w;
                }
                #pragma unroll
                for (int it = 0; it < 2; it++) {
                    int idx = tid + it * 128;
                    int r   = idx >> 2;
                    int kq  = idx & 3;
                    Bw[(kq * 4 + 0) * LDB + r] = pb[it].x;
                    Bw[(kq * 4 + 1) * LDB + r] = pb[it].y;
                    Bw[(kq * 4 + 2) * LDB + r] = pb[it].z;
                    Bw[(kq * 4 + 3) * LDB + r] = pb[it].w;
                }
            }
            __syncthreads();
        }

        // ---- stage + scan in two 64-row halves ----
        #pragma unroll
        for (int h = 0; h < 2; h++) {
            if ((ty >> 3) == h) {
                const int lty = ty & 7;
                #pragma unroll
                for (int i = 0; i < 8; i++) {
                    const int lr = lty * 8 + i;
                    float2 c0 = unpack2(acc2[i][0]);
                    float2 c1 = unpack2(acc2[i][1]);
                    float2 c2 = unpack2(acc2[i][2]);
                    float2 c3 = unpack2(acc2[i][3]);
                    float* sr = &stg[lr * LDS_STG + tx * 8];
                    *(float2*)(sr + 0) = make_float2(c0.x + rbias[0], c0.y + rbias[1]);
                    *(float2*)(sr + 2) = make_float2(c1.x + rbias[2], c1.y + rbias[3]);
                    *(float2*)(sr + 4) = make_float2(c2.x + rbias[4], c2.y + rbias[5]);
                    *(float2*)(sr + 6) = make_float2(c3.x + rbias[6], c3.y + rbias[7]);
                }
            }
            __syncthreads();

            if (tid < 64) {
                float* op = out + (size_t)(b * T_ + t0 + h * 64) * DOUT + n0 + tid;
                float m2 = mem;
                int   c2 = 0;
                #pragma unroll 8
                for (int tl = 0; tl < 64; tl++) {
                    float cur = stg[tl * LDS_STG + tid];
                    m2 = BETA * m2 + cur;
                    float s = (m2 > THRESH) ? 1.0f : 0.0f;
                    m2 -= s;
                    op[(size_t)tl * DOUT] = s;
                    c2 += (s > 0.5f) ? 1 : 0;
                }
                mem = m2;
                cnt += c2;
            }
            __syncthreads();
        }
    }

    // ---- deterministic spike-count reduction (warps 0 and 1) ----
    if (tid < 64) {
        #pragma unroll
        for (int o = 16; o > 0; o >>= 1)
            cnt += __shfl_down_sync(0xffffffffu, cnt, o);
    }
    __shared__ int red[2];
    if (tid == 0 || tid == 32) red[tid >> 5] = cnt;
    __syncthreads();
    if (tid == 0) atomicAdd(&g_count, red[0] + red[1]);
}

__global__ void zero_count_kernel() { g_count = 0; }

__global__ void finalize_kernel(float* __restrict__ out, int out_size)
{
    if ((size_t)out_size > N_SPK)
        out[N_SPK] = (float)g_count;
}

// ---------------------------------------------------------------------------
extern "C" void kernel_launch(void* const* d_in, const int* in_sizes, int n_in,
                              void* d_out, int out_size)
{
    const float* x    = (const float*)d_in[0];   // [B, T, DIN]
    const float* W    = (const float*)d_in[1];   // [DOUT, DIN]
    const float* bias = (const float*)d_in[2];   // [DOUT]
    float* out = (float*)d_out;
    (void)in_sizes; (void)n_in;

    cudaFuncSetAttribute(fused_kernel,
                         cudaFuncAttributeMaxDynamicSharedMemorySize, SMEM_BYTES);

    zero_count_kernel<<<1, 1>>>();

    dim3 grid(DOUT / 64, B_);          // (8, 128) = 1024 CTAs, n fastest
    fused_kernel<<<grid, 128, SMEM_BYTES>>>(x, W, bias, out);

    finalize_kernel<<<1, 1>>>(out, out_size);
}